// round 4
// baseline (speedup 1.0000x reference)
#include <cuda_runtime.h>
#include <cstdint>

// Problem constants (HQQGroupedGemm_37357625540844)
#define E_   8
#define T_   2048
#define IN_  2048
#define OUT_ 2048
#define GS_  64
#define G_   (IN_ / GS_)

// Tiling
#define BM 128
#define BN 128
#define BK 32
#define NTHREADS 320              // 8 consumer warps + 2 producer warps
#define NCONS 256
#define KSTEPS (IN_ / BK)         // 64

#define AS_STRIDE 36              // fp32 A tile rows (32 + 4 pad)
#define BS_STRIDE 136             // tf32 B tile rows (128 + 8 pad)
#define A_TILE (BM * AS_STRIDE)   // floats per A buffer
#define B_TILE (BK * BS_STRIDE)   // floats per B buffer
#define SMEM_BYTES ((2 * A_TILE + 2 * B_TILE) * 4)   // 71680

// Named barriers: ping-pong full/empty per buffer
#define BAR_FULL0  0
#define BAR_FULL1  1
#define BAR_EMPTY0 2
#define BAR_EMPTY1 3

__device__ __forceinline__ void bar_sync_n(int id) {
    asm volatile("bar.sync %0, %1;" :: "r"(id), "r"(NTHREADS) : "memory");
}
__device__ __forceinline__ void bar_arrive_n(int id) {
    asm volatile("bar.arrive %0, %1;" :: "r"(id), "r"(NTHREADS) : "memory");
}

__device__ __forceinline__ unsigned f2tf(float f) {
    unsigned u;
    asm("cvt.rna.tf32.f32 %0, %1;" : "=r"(u) : "f"(f));
    return u;
}

__device__ __forceinline__ void mma_tf32(float* c, const unsigned* a, const unsigned* b) {
    asm volatile(
        "mma.sync.aligned.m16n8k8.row.col.f32.tf32.tf32.f32 "
        "{%0,%1,%2,%3}, {%4,%5,%6,%7}, {%8,%9}, {%0,%1,%2,%3};"
        : "+f"(c[0]), "+f"(c[1]), "+f"(c[2]), "+f"(c[3])
        : "r"(a[0]), "r"(a[1]), "r"(a[2]), "r"(a[3]), "r"(b[0]), "r"(b[1]));
}

__device__ __forceinline__ void cpasync16(float* s, const float* g) {
    unsigned saddr = (unsigned)__cvta_generic_to_shared(s);
    asm volatile("cp.async.cg.shared.global [%0], [%1], 16;" :: "r"(saddr), "l"(g));
}
__device__ __forceinline__ void cpcommit() { asm volatile("cp.async.commit_group;"); }
__device__ __forceinline__ void cpwait0()  { asm volatile("cp.async.wait_group 0;" ::: "memory"); }

extern __shared__ float smem[];

__global__ void __launch_bounds__(NTHREADS, 2)
hqq_ws_kernel(const float* __restrict__ x,
              const int*   __restrict__ qw,
              const float* __restrict__ sz,
              const int*   __restrict__ tpe,
              float*       __restrict__ out)
{
    const int e  = blockIdx.z;
    const int mb = blockIdx.y;
    const int nb = blockIdx.x;

    // expert row range from tokens_per_expert prefix sum (uniform per block)
    int r0 = 0, cnt_e = 0;
#pragma unroll
    for (int i = 0; i < E_; i++) {
        int c = __ldg(&tpe[i]);
        if (i < e) r0 += c;
        if (i == e) cnt_e = c;
    }
    const int mlo = max(r0, mb * BM);
    const int mhi = min(r0 + cnt_e, mb * BM + BM);
    if (mlo >= mhi) return;

    float* As = smem;                 // [2][BM][AS_STRIDE], raw fp32
    float* Bs = smem + 2 * A_TILE;    // [2][BK][BS_STRIDE], tf32 bits

    const int tid  = threadIdx.x;
    const int warp = tid >> 5, lane = tid & 31;

    if (warp < 8) {
        // ================= CONSUMER: 8 warps, 4x2 grid of 32x64 tiles =====
        const int wm = warp >> 1, wn = warp & 1;
        const int gid = lane >> 2, tig = lane & 3;
        const bool wactive = (mb * BM + wm * 32 < mhi) && (mb * BM + wm * 32 + 32 > mlo);

        float acc[2][8][4];
#pragma unroll
        for (int mt = 0; mt < 2; mt++)
#pragma unroll
            for (int nt = 0; nt < 8; nt++)
#pragma unroll
                for (int q = 0; q < 4; q++) acc[mt][nt][q] = 0.0f;

#pragma unroll 1
        for (int s = 0; s < KSTEPS; s++) {
            bar_sync_n(BAR_FULL0 + (s & 1));
            if (wactive) {
                const float* AsC = As + (s & 1) * A_TILE;
                const float* BsC = Bs + (s & 1) * B_TILE;
#pragma unroll
                for (int ksub = 0; ksub < 4; ksub++) {
                    const int kk = ksub * 8 + tig;
                    unsigned a[2][4];
#pragma unroll
                    for (int mt = 0; mt < 2; mt++) {
                        int r = wm * 32 + mt * 16 + gid;
                        a[mt][0] = f2tf(AsC[(r)     * AS_STRIDE + kk]);
                        a[mt][1] = f2tf(AsC[(r + 8) * AS_STRIDE + kk]);
                        a[mt][2] = f2tf(AsC[(r)     * AS_STRIDE + kk + 4]);
                        a[mt][3] = f2tf(AsC[(r + 8) * AS_STRIDE + kk + 4]);
                    }
#pragma unroll
                    for (int nt = 0; nt < 8; nt++) {
                        int cc = wn * 64 + nt * 8 + gid;
                        unsigned b[2];
                        b[0] = __float_as_uint(BsC[(kk)     * BS_STRIDE + cc]);
                        b[1] = __float_as_uint(BsC[(kk + 4) * BS_STRIDE + cc]);
                        mma_tf32(acc[0][nt], a[0], b);
                        mma_tf32(acc[1][nt], a[1], b);
                    }
                }
            }
            bar_arrive_n(BAR_EMPTY0 + (s & 1));
        }

        // epilogue: masked stores of valid expert rows
#pragma unroll
        for (int mt = 0; mt < 2; mt++) {
#pragma unroll
            for (int nt = 0; nt < 8; nt++) {
                int row0 = mb * BM + wm * 32 + mt * 16 + gid;
                int col  = nb * BN + wn * 64 + nt * 8 + tig * 2;
                if (row0 >= mlo && row0 < mhi) {
                    float2 v = make_float2(acc[mt][nt][0], acc[mt][nt][1]);
                    *reinterpret_cast<float2*>(out + (size_t)row0 * OUT_ + col) = v;
                }
                int row1 = row0 + 8;
                if (row1 >= mlo && row1 < mhi) {
                    float2 v = make_float2(acc[mt][nt][2], acc[mt][nt][3]);
                    *reinterpret_cast<float2*>(out + (size_t)row1 * OUT_ + col) = v;
                }
            }
        }
    } else {
        // ================= PRODUCER: 2 warps (64 threads) =================
        const int ptid = tid - NCONS;          // 0..63
        const int pw = ptid >> 5, pl = ptid & 31;

        const float* xB  = x + (size_t)(mb * BM) * IN_;
        const int ncol   = nb * BN + pl * 4;
        const int* qB    = qw + (size_t)e * IN_ * OUT_ + ncol;
        const float* szp = sz + (size_t)e * G_ * OUT_ * 2 + (size_t)ncol * 2;

        int4 qv[4][4];   // [kh][j]: rows pw*4 + kh*8 + j, 4 cols at pl*4
        auto loadQ = [&](int s) {
            const int k0 = s * BK;
#pragma unroll
            for (int kh = 0; kh < 4; kh++)
#pragma unroll
                for (int j = 0; j < 4; j++)
                    qv[kh][j] = *reinterpret_cast<const int4*>(
                        qB + (size_t)(k0 + pw * 4 + kh * 8 + j) * OUT_);
        };

        loadQ(0);
#pragma unroll 1
        for (int s = 0; s < KSTEPS; s++) {
            if (s >= 2) bar_sync_n(BAR_EMPTY0 + (s & 1));
            float* AsN = As + (s & 1) * A_TILE;
            float* BsN = Bs + (s & 1) * B_TILE;
            const int k0 = s * BK;

            // A: raw fp32 cp.async, 2 rows x 8 x 16B chunks per thread
#pragma unroll
            for (int rr = 0; rr < 2; rr++) {
                int row = ptid * 2 + rr;
                const float* src = xB + (size_t)row * IN_ + k0;
                float* dst = AsN + row * AS_STRIDE;
#pragma unroll
                for (int h = 0; h < 8; h++)
                    cpasync16(dst + h * 4, src + h * 4);
            }
            cpcommit();

            // scales/zeros for this k-group (L1-hot on repeats)
            const float* sq = szp + (size_t)(s >> 1) * OUT_ * 2;
            float4 u = __ldg(reinterpret_cast<const float4*>(sq));
            float4 v = __ldg(reinterpret_cast<const float4*>(sq + 4));
            float4 sc = make_float4(u.x, u.z, v.x, v.z);
            float4 zc = make_float4(fmaf(-8.f, u.x, u.y), fmaf(-8.f, u.z, u.w),
                                    fmaf(-8.f, v.x, v.y), fmaf(-8.f, v.z, v.w));

            // B: dequant int4 codes -> tf32 bits, k-major STS.128 (conflict-free)
#pragma unroll
            for (int kh = 0; kh < 4; kh++) {
#pragma unroll
                for (int j = 0; j < 4; j++) {
                    int4 q = qv[kh][j];
                    uint4 w;
                    w.x = f2tf(fmaf((float)q.x, sc.x, zc.x));
                    w.y = f2tf(fmaf((float)q.y, sc.y, zc.y));
                    w.z = f2tf(fmaf((float)q.z, sc.z, zc.z));
                    w.w = f2tf(fmaf((float)q.w, sc.w, zc.w));
                    int r = pw * 4 + kh * 8 + j;
                    *reinterpret_cast<uint4*>(BsN + r * BS_STRIDE + pl * 4) = w;
                }
            }

            cpwait0();                       // A tile landed
            bar_arrive_n(BAR_FULL0 + (s & 1));
            if (s + 1 < KSTEPS) loadQ(s + 1);   // prefetch next stage codes
        }
    }
}

extern "C" void kernel_launch(void* const* d_in, const int* in_sizes, int n_in,
                              void* d_out, int out_size) {
    (void)in_sizes; (void)n_in; (void)out_size;
    const float* x   = (const float*)d_in[0];
    const int*   qw  = (const int*)d_in[1];
    const float* sz  = (const float*)d_in[2];
    const int*   tpe = (const int*)d_in[3];
    float*       out = (float*)d_out;

    cudaFuncSetAttribute(hqq_ws_kernel,
                         cudaFuncAttributeMaxDynamicSharedMemorySize, SMEM_BYTES);

    dim3 grid(OUT_ / BN, T_ / BM, E_);
    hqq_ws_kernel<<<grid, NTHREADS, SMEM_BYTES>>>(x, qw, sz, tpe, out);
}

// round 7
// speedup vs baseline: 1.1487x; 1.1487x over previous
#include <cuda_runtime.h>
#include <cstdint>

// Problem constants (HQQGroupedGemm_37357625540844)
#define E_   8
#define T_   2048
#define IN_  2048
#define OUT_ 2048
#define GS_  64
#define G_   (IN_ / GS_)

// Tiling
#define BM 128
#define BN 128
#define BK 32
#define NTHREADS 256
#define KSTEPS (IN_ / BK)      // 64
#define AS_STRIDE 36           // 32 + 4 pad floats: conflict-free A frag LDS
#define BS_STRIDE 136          // 128 + 8 pad floats: conflict-free B frag LDS
#define A_TILE (BM * AS_STRIDE)
#define B_TILE (BK * BS_STRIDE)
#define SMEM_BYTES ((2 * A_TILE + 2 * B_TILE) * 4)  // 71680

__device__ __forceinline__ unsigned f2tf(float f) {
    unsigned u;
    asm("cvt.rna.tf32.f32 %0, %1;" : "=r"(u) : "f"(f));
    return u;
}

__device__ __forceinline__ void mma_tf32(float* c, const unsigned* a, const unsigned* b) {
    asm volatile(
        "mma.sync.aligned.m16n8k8.row.col.f32.tf32.tf32.f32 "
        "{%0,%1,%2,%3}, {%4,%5,%6,%7}, {%8,%9}, {%0,%1,%2,%3};"
        : "+f"(c[0]), "+f"(c[1]), "+f"(c[2]), "+f"(c[3])
        : "r"(a[0]), "r"(a[1]), "r"(a[2]), "r"(a[3]), "r"(b[0]), "r"(b[1]));
}

__device__ __forceinline__ void cpasync16(float* s, const float* g) {
    unsigned saddr = (unsigned)__cvta_generic_to_shared(s);
    asm volatile("cp.async.cg.shared.global [%0], [%1], 16;" :: "r"(saddr), "l"(g));
}
__device__ __forceinline__ void cpcommit() { asm volatile("cp.async.commit_group;"); }
__device__ __forceinline__ void cpwait0()  { asm volatile("cp.async.wait_group 0;" ::: "memory"); }

extern __shared__ float smem[];

__global__ void __launch_bounds__(NTHREADS, 2)
hqq_grouped_gemm_kernel(const float* __restrict__ x,
                        const int*   __restrict__ qw,
                        const float* __restrict__ sz,
                        const int*   __restrict__ tpe,
                        float*       __restrict__ out)
{
    const int e  = blockIdx.z;
    const int mb = blockIdx.y;
    const int nb = blockIdx.x;

    // Expert row range (uniform per block)
    int r0 = 0, cnt_e = 0;
#pragma unroll
    for (int i = 0; i < E_; i++) {
        int c = __ldg(&tpe[i]);
        if (i < e) r0 += c;
        if (i == e) cnt_e = c;
    }
    const int mlo = max(r0, mb * BM);
    const int mhi = min(r0 + cnt_e, mb * BM + BM);
    if (mlo >= mhi) return;

    // 32-row band activity (band p = rows mb*128 + [p*32, p*32+32))
    bool bandAct[4];
#pragma unroll
    for (int p = 0; p < 4; p++) {
        int b0 = mb * BM + p * 32;
        bandAct[p] = (b0 < mhi) && (b0 + 32 > mlo);
    }

    float* As = smem;                 // [2][BM][AS_STRIDE]
    float* Bs = smem + 2 * A_TILE;    // [2][BK][BS_STRIDE]

    const int tid  = threadIdx.x;
    const int warp = tid >> 5, lane = tid & 31;
    const int wm   = warp >> 1, wn = warp & 1;     // 4x2 warps, 32x64 tiles
    const int gid  = lane >> 2, tig = lane & 3;
    const bool wactive = bandAct[wm];

    // B dequant mapping: thread writes 4 rows x 4 cols
    const int cg   = tid & 31;
    const int rb   = (tid >> 5) * 4;
    const int ncol = nb * BN + cg * 4;

    const int* qp = qw + (size_t)e * IN_ * OUT_ + (size_t)rb * OUT_ + ncol;
    const float* szp = sz + (size_t)e * G_ * OUT_ * 2 + (size_t)ncol * 2;

    auto loadA = [&](int i, float* dst) {     // iteration j covers exactly band j
        const int k0 = i * BK;
#pragma unroll
        for (int j = 0; j < 4; j++) {
            if (!bandAct[j]) continue;        // skip unused rows entirely
            int row = j * 32 + (tid >> 3);
            int kc  = tid & 7;
            cpasync16(dst + row * AS_STRIDE + kc * 4,
                      x + (size_t)(mb * BM + row) * IN_ + k0 + kc * 4);
        }
    };

    int4 qv[4];
    auto loadQ = [&](int i) {
        const int k0 = i * BK;
#pragma unroll
        for (int j = 0; j < 4; j++)
            qv[j] = *reinterpret_cast<const int4*>(qp + (size_t)(k0 + j) * OUT_);
    };

    float4 sc, zc;
    auto loadSZ = [&](int g) {
        const float* q2 = szp + (size_t)g * OUT_ * 2;
        float4 u = __ldg(reinterpret_cast<const float4*>(q2));
        float4 v = __ldg(reinterpret_cast<const float4*>(q2 + 4));
        sc = make_float4(u.x, u.z, v.x, v.z);
        zc = make_float4(fmaf(-8.f, u.x, u.y), fmaf(-8.f, u.z, u.w),
                         fmaf(-8.f, v.x, v.y), fmaf(-8.f, v.z, v.w));
    };

    auto dequant_j = [&](float* dst, int j) {  // one STS.128 quad
        int4 q = qv[j];
        uint4 w;
        w.x = f2tf(fmaf((float)q.x, sc.x, zc.x));
        w.y = f2tf(fmaf((float)q.y, sc.y, zc.y));
        w.z = f2tf(fmaf((float)q.z, sc.z, zc.z));
        w.w = f2tf(fmaf((float)q.w, sc.w, zc.w));
        *reinterpret_cast<uint4*>(dst + (rb + j) * BS_STRIDE + cg * 4) = w;
    };

    float acc[2][8][4];
#pragma unroll
    for (int mt = 0; mt < 2; mt++)
#pragma unroll
        for (int nt = 0; nt < 8; nt++)
#pragma unroll
            for (int q = 0; q < 4; q++) acc[mt][nt][q] = 0.0f;

    // ---- prologue: fill buf0 (stage 0), prefetch codes for stage 1 -------
    loadA(0, As);
    cpcommit();
    loadQ(0);
    loadSZ(0);
#pragma unroll
    for (int j = 0; j < 4; j++) dequant_j(Bs, j);
    loadQ(1);                     // consumed by interleaved dequant at s=0
    cpwait0();
    __syncthreads();

    // ---- main loop --------------------------------------------------------
#pragma unroll 1
    for (int s = 0; s < KSTEPS; s++) {
        const float* AsC = As + (s & 1) * A_TILE;
        const float* BsC = Bs + (s & 1) * B_TILE;
        float* AsN = As + ((s + 1) & 1) * A_TILE;
        float* BsN = Bs + ((s + 1) & 1) * B_TILE;
        const bool hasN = (s + 1 < KSTEPS);

        if (hasN) { loadA(s + 1, AsN); cpcommit(); }

        // MMA over cur buffer, interleaved with dequant of stage s+1 into nxt
#pragma unroll
        for (int ksub = 0; ksub < 4; ksub++) {
            if (wactive) {
                const int kk = ksub * 8 + tig;
                unsigned a[2][4];
#pragma unroll
                for (int mt = 0; mt < 2; mt++) {
                    int r = wm * 32 + mt * 16 + gid;
                    a[mt][0] = f2tf(AsC[(r)     * AS_STRIDE + kk]);
                    a[mt][1] = f2tf(AsC[(r + 8) * AS_STRIDE + kk]);
                    a[mt][2] = f2tf(AsC[(r)     * AS_STRIDE + kk + 4]);
                    a[mt][3] = f2tf(AsC[(r + 8) * AS_STRIDE + kk + 4]);
                }
#pragma unroll
                for (int nt = 0; nt < 8; nt++) {
                    int cc = wn * 64 + nt * 8 + gid;
                    unsigned b[2];
                    b[0] = __float_as_uint(BsC[(kk)     * BS_STRIDE + cc]);
                    b[1] = __float_as_uint(BsC[(kk + 4) * BS_STRIDE + cc]);
                    mma_tf32(acc[0][nt], a[0], b);
                    mma_tf32(acc[1][nt], a[1], b);
                }
            }
            if (hasN) dequant_j(BsN, ksub);   // overlap ALU/STS with tensor queue
        }

        // prefetch codes for stage s+2 (full stage of latency cover)
        if (s + 2 < KSTEPS) {
            loadQ(s + 2);
            if (((s + 2) & 1) == 0) loadSZ((s + 2) >> 1);
        }
        if (hasN) cpwait0();
        __syncthreads();
    }

    // ---- epilogue: masked stores ------------------------------------------
    if (wactive) {
#pragma unroll
        for (int mt = 0; mt < 2; mt++) {
#pragma unroll
            for (int nt = 0; nt < 8; nt++) {
                int row0 = mb * BM + wm * 32 + mt * 16 + gid;
                int col  = nb * BN + wn * 64 + nt * 8 + tig * 2;
                if (row0 >= mlo && row0 < mhi) {
                    float2 v = make_float2(acc[mt][nt][0], acc[mt][nt][1]);
                    *reinterpret_cast<float2*>(out + (size_t)row0 * OUT_ + col) = v;
                }
                int row1 = row0 + 8;
                if (row1 >= mlo && row1 < mhi) {
                    float2 v = make_float2(acc[mt][nt][2], acc[mt][nt][3]);
                    *reinterpret_cast<float2*>(out + (size_t)row1 * OUT_ + col) = v;
                }
            }
        }
    }
}

extern "C" void kernel_launch(void* const* d_in, const int* in_sizes, int n_in,
                              void* d_out, int out_size) {
    (void)in_sizes; (void)n_in; (void)out_size;
    const float* x   = (const float*)d_in[0];
    const int*   qw  = (const int*)d_in[1];
    const float* sz  = (const float*)d_in[2];
    const int*   tpe = (const int*)d_in[3];
    float*       out = (float*)d_out;

    cudaFuncSetAttribute(hqq_grouped_gemm_kernel,
                         cudaFuncAttributeMaxDynamicSharedMemorySize, SMEM_BYTES);

    dim3 grid(OUT_ / BN, T_ / BM, E_);
    hqq_grouped_gemm_kernel<<<grid, NTHREADS, SMEM_BYTES>>>(x, qw, sz, tpe, out);
}